// round 1
// baseline (speedup 1.0000x reference)
#include <cuda_runtime.h>
#include <math.h>

#define NB 32
#define NL 1024
#define NC 512
#define LH 512   // L/2

// ---------------- scratch (device globals; no allocations) ----------------
__device__ float g_res[(size_t)2*NB*NC*NL];     // [2][B][C][L]
__device__ float g_cv [(size_t)NB*NC*86];       // conv out interleaved [B][C][2ne]
__device__ float g_x1 [(size_t)NB*NC*85];       // [B][C][m]
__device__ float g_xf [(size_t)NB*NC*169];      // [B][C][2m-1]
__device__ float g_xi [(size_t)NB*NC*85];
__device__ float g_xr [(size_t)NB*NC*85];
__device__ float g_yln[(size_t)NB*NC*85];
__device__ float g_y2 [(size_t)NB*NC*1032];     // [B][C][m*k]
__device__ float g_br [(size_t)NB*NL*2*NC];     // [B*L][2*C] (branch outputs, merge-ready)
__device__ float g_mg [(size_t)NB*NL*NC];
__device__ float g_h1 [(size_t)NB*NL*4*NC];
__device__ float g_h2 [(size_t)NB*NL*NC];
__device__ float g_W2 [(size_t)NC*24*NC];       // transposed conv-transpose weights
__device__ float g_Wm [(size_t)2*NC*NC];        // transposed merge weights
__device__ float g_CM [85*169];                 // real-DFT matrix (per-branch rebuilt)
__device__ float g_CM2[85*85];                  // real-IDFT matrix

// ---------------- series decomp: res[n] = src - movavg(src, {17,33}), transposed to [B][C][L]
__global__ void decomp_kernel(const float* __restrict__ src, float* __restrict__ res) {
    __shared__ float s[64][33];
    int b = blockIdx.z;
    int c0 = blockIdx.y * 32;
    int l0 = blockIdx.x * 32;
    int tx = threadIdx.x, ty = threadIdx.y;
    for (int r = ty; r < 64; r += 32) {
        int l = l0 - 16 + r;
        l = l < 0 ? 0 : (l > NL - 1 ? NL - 1 : l);
        s[r][tx] = src[((size_t)b*NL + l)*NC + c0 + tx];
    }
    __syncthreads();
    int base = tx + 16;
    float s17 = 0.f;
    #pragma unroll
    for (int j = -8; j <= 8; j++) s17 += s[base + j][ty];
    float s33 = s17;
    #pragma unroll
    for (int j = 9; j <= 16; j++) s33 += s[base - j][ty] + s[base + j][ty];
    float v = s[base][ty];
    size_t o = ((size_t)(b*NC + c0 + ty))*NL + l0 + tx;
    res[o] = v - s17 / 17.0f;
    res[(size_t)NB*NC*NL + o] = v - s33 / 33.0f;
}

// ---------------- weight prep ----------------
__global__ void prep_trw_k(const float* __restrict__ tw, float* __restrict__ W2, int k) {
    int total = NC*NC*k;
    for (int idx = blockIdx.x*blockDim.x + threadIdx.x; idx < total; idx += gridDim.x*blockDim.x) {
        int cin = idx / (NC*k);
        int r   = idx - cin*(NC*k);          // cout*k + j
        W2[(size_t)r*NC + cin] = tw[idx];
    }
}
__global__ void prep_merge_k(const float* __restrict__ mwt, float* __restrict__ Wm) {
    int total = NC*NC*2;
    for (int idx = blockIdx.x*blockDim.x + threadIdx.x; idx < total; idx += gridDim.x*blockDim.x) {
        int o = idx / (NC*2);
        int rem = idx - o*NC*2;
        int c = rem >> 1, n = rem & 1;
        Wm[((size_t)n*NC + c)*NC + o] = mwt[idx];
    }
}
__global__ void build_cm_k(float* __restrict__ CM, float* __restrict__ CM2, int m, int N2) {
    const double TWO_PI = 6.283185307179586476925286766559;
    int t1 = m*N2, t2 = m*m;
    for (int idx = blockIdx.x*blockDim.x + threadIdx.x; idx < t1 + t2; idx += gridDim.x*blockDim.x) {
        if (idx < t1) {
            int t = idx / N2, f = idx - t*N2;
            CM[idx] = (float)cos(TWO_PI * (double)((long long)f*(t + m - 1)) / (double)N2);
        } else {
            int i2 = idx - t1;
            int f = i2 / m, t = i2 - f*m;
            CM2[i2] = (float)(cos(TWO_PI * (double)((long long)f*t) / (double)m) / (double)m);
        }
    }
}

// ---------------- x1: exp-gated interleave, drop last ----------------
__global__ void x1_kernel(const float* __restrict__ cv, float* __restrict__ x1, int m, int ne2) {
    size_t total = (size_t)NB*NC*m;
    for (size_t idx = (size_t)blockIdx.x*blockDim.x + threadIdx.x; idx < total;
         idx += (size_t)gridDim.x*blockDim.x) {
        int t = (int)(idx % m);
        size_t bc = idx / m;
        const float* c2 = cv + bc*ne2;
        x1[idx] = c2[t ^ 1] * expf(c2[t]);
    }
}

// ---------------- generic tiled fp32 GEMM with pluggable loaders/epilogues ----
struct GemmP {
    const float* A; int lda;
    const float* Bp; int ldb; long long sBb;
    float* D; long long sDb; int ldd;
    const float* bias;
    int M, N, K;
    int npos;                       // N = nbatch * npos
    int kker, pad, lhalf, inner;    // im2col params
    int kt, mklen;                  // transconv store params
};

// BMODE: 0 dense, 1 conv-im2col(even/odd), 2 iso-im2col
// BIASM: 0 none, 1 per-row, 2 per-col(q), 3 bias[row/kt]
// ACT: 0 none, 1 tanh, 2 relu
// SMODE: 0 normal, 1 transconv scatter
template<int BMODE, int BIASM, int ACT, int SMODE>
__global__ void gemm_k(GemmP p) {
    constexpr int BK = 16;
    __shared__ float  As[BK][65];
    __shared__ float4 Bs4[BK][16];
    const int tid = threadIdx.x;
    const int tx = tid & 15, ty = tid >> 4;
    const int m0 = blockIdx.y * 64, n0 = blockIdx.x * 64;
    const int arow = tid >> 2, acol = (tid & 3) * 4;
    const int brow = tid >> 4, bcol = (tid & 15) * 4;
    float acc[4][4] = {};

    for (int k0 = 0; k0 < p.K; k0 += BK) {
        {
            int gm = m0 + arow;
            #pragma unroll
            for (int i = 0; i < 4; i++) {
                int gk = k0 + acol + i;
                float v = 0.f;
                if (gm < p.M && gk < p.K) v = p.A[(long long)gm*p.lda + gk];
                As[acol + i][arow] = v;
            }
        }
        {
            int gk = k0 + brow;
            float vv[4];
            #pragma unroll
            for (int j = 0; j < 4; j++) {
                int gn = n0 + bcol + j;
                float v = 0.f;
                if (gk < p.K && gn < p.N) {
                    int b, q;
                    if (BMODE == 0 && p.sBb == 0) { b = 0; q = gn; }
                    else { b = gn / p.npos; q = gn - b*p.npos; }
                    if (BMODE == 0) {
                        v = p.Bp[b*p.sBb + (long long)gk*p.ldb + q];
                    } else if (BMODE == 1) {
                        int cin = gk / p.kker, t = gk - cin*p.kker;
                        int o = q >> 1, pb = q & 1;
                        int s = o*p.kker - p.pad + t;
                        if (s >= 0 && s < p.lhalf)
                            v = p.Bp[b*p.sBb + (long long)cin*p.inner + 2*s + pb];
                    } else {
                        int cin = gk / p.kker, t = gk - cin*p.kker;
                        v = p.Bp[b*p.sBb + (long long)cin*p.inner + t + q];
                    }
                }
                vv[j] = v;
            }
            Bs4[brow][bcol >> 2] = make_float4(vv[0], vv[1], vv[2], vv[3]);
        }
        __syncthreads();
        #pragma unroll
        for (int kk = 0; kk < BK; kk++) {
            float a[4], bb[4];
            #pragma unroll
            for (int i = 0; i < 4; i++) a[i] = As[kk][ty*4 + i];
            float4 bv = Bs4[kk][tx];
            bb[0] = bv.x; bb[1] = bv.y; bb[2] = bv.z; bb[3] = bv.w;
            #pragma unroll
            for (int i = 0; i < 4; i++)
                #pragma unroll
                for (int j = 0; j < 4; j++)
                    acc[i][j] = fmaf(a[i], bb[j], acc[i][j]);
        }
        __syncthreads();
    }
    #pragma unroll
    for (int i = 0; i < 4; i++) {
        int row = m0 + ty*4 + i;
        if (row >= p.M) continue;
        #pragma unroll
        for (int j = 0; j < 4; j++) {
            int gn = n0 + tx*4 + j;
            if (gn >= p.N) continue;
            int b, q;
            if (SMODE == 0 && p.sDb == 0) { b = 0; q = gn; }
            else { b = gn / p.npos; q = gn - b*p.npos; }
            float v = acc[i][j];
            if (BIASM == 1) v += p.bias[row];
            else if (BIASM == 2) v += p.bias[q];
            else if (BIASM == 3) v += p.bias[row / p.kt];
            if (ACT == 1) v = tanhf(v);
            else if (ACT == 2) v = fmaxf(v, 0.f);
            long long addr;
            if (SMODE == 0) addr = b*p.sDb + (long long)row*p.ldd + q;
            else {
                int cout = row / p.kt, jj = row - cout*p.kt;
                addr = b*p.sDb + (long long)cout*p.mklen + (long long)q*p.kt + jj;
            }
            p.D[addr] = v;
        }
    }
}

// ---------------- block reduce + layer norms (256 threads, C=512) ----------
__device__ __forceinline__ float blk_sum(float v) {
    __shared__ float sb[8];
    #pragma unroll
    for (int o = 16; o; o >>= 1) v += __shfl_xor_sync(0xffffffffu, v, o);
    if ((threadIdx.x & 31) == 0) sb[threadIdx.x >> 5] = v;
    __syncthreads();
    float t = 0.f;
    #pragma unroll
    for (int i = 0; i < 8; i++) t += sb[i];
    __syncthreads();
    return t;
}

__global__ void ln1_kernel(const float* __restrict__ xr, const float* __restrict__ x1,
                           const float* __restrict__ g, const float* __restrict__ bt,
                           float* __restrict__ out, int m) {
    int row = blockIdx.x;               // B*m
    int b = row / m, t = row - b*m;
    int tid = threadIdx.x;
    size_t base = (size_t)b*NC*m + t;
    float v0 = xr[base + (size_t)tid*m]       + x1[base + (size_t)tid*m];
    float v1 = xr[base + (size_t)(tid+256)*m] + x1[base + (size_t)(tid+256)*m];
    float mu = blk_sum(v0 + v1) * (1.f/NC);
    float d0 = v0 - mu, d1 = v1 - mu;
    float var = blk_sum(d0*d0 + d1*d1) * (1.f/NC);
    float inv = rsqrtf(var + 1e-5f);
    out[base + (size_t)tid*m]       = d0*inv*g[tid]     + bt[tid];
    out[base + (size_t)(tid+256)*m] = d1*inv*g[tid+256] + bt[tid+256];
}

__global__ void branch_out_kernel(const float* __restrict__ y2, const float* __restrict__ resn,
                                  const float* __restrict__ g, const float* __restrict__ bt,
                                  float* __restrict__ br, int mk, int nbr) {
    int row = blockIdx.x;               // B*L
    int b = row >> 10, l = row & 1023;
    int li = (l * mk) >> 10;            // exact nearest-interp index
    int tid = threadIdx.x;
    size_t yb = (size_t)b*NC*mk + li;
    size_t rb = (size_t)b*NC*NL + l;
    float v0 = y2[yb + (size_t)tid*mk]       + resn[rb + (size_t)tid*NL];
    float v1 = y2[yb + (size_t)(tid+256)*mk] + resn[rb + (size_t)(tid+256)*NL];
    float mu = blk_sum(v0 + v1) * (1.f/NC);
    float d0 = v0 - mu, d1 = v1 - mu;
    float var = blk_sum(d0*d0 + d1*d1) * (1.f/NC);
    float inv = rsqrtf(var + 1e-5f);
    float* o = br + (size_t)row*(2*NC) + nbr*NC;
    o[tid]     = d0*inv*g[tid]     + bt[tid];
    o[tid+256] = d1*inv*g[tid+256] + bt[tid+256];
}

__global__ void final_ln_kernel(const float* __restrict__ mg, const float* __restrict__ h2,
                                const float* __restrict__ g, const float* __restrict__ bt,
                                float* __restrict__ out) {
    int row = blockIdx.x;               // B*L
    int tid = threadIdx.x;
    size_t base = (size_t)row*NC;
    float v0 = mg[base + tid]       + h2[base + tid];
    float v1 = mg[base + tid + 256] + h2[base + tid + 256];
    float mu = blk_sum(v0 + v1) * (1.f/NC);
    float d0 = v0 - mu, d1 = v1 - mu;
    float var = blk_sum(d0*d0 + d1*d1) * (1.f/NC);
    float inv = rsqrtf(var + 1e-5f);
    out[base + tid]       = d0*inv*g[tid]     + bt[tid];
    out[base + tid + 256] = d1*inv*g[tid+256] + bt[tid+256];
}

static inline dim3 gemm_grid(int M, int N) { return dim3((N + 63)/64, (M + 63)/64, 1); }

extern "C" void kernel_launch(void* const* d_in, const int* in_sizes, int n_in,
                              void* d_out, int out_size) {
    (void)in_sizes; (void)n_in; (void)out_size;
    const float* src   = (const float*)d_in[0];
    const float* cw[2] = {(const float*)d_in[1],  (const float*)d_in[7]};
    const float* cb[2] = {(const float*)d_in[2],  (const float*)d_in[8]};
    const float* iw[2] = {(const float*)d_in[3],  (const float*)d_in[9]};
    const float* ib[2] = {(const float*)d_in[4],  (const float*)d_in[10]};
    const float* tw[2] = {(const float*)d_in[5],  (const float*)d_in[11]};
    const float* tb[2] = {(const float*)d_in[6],  (const float*)d_in[12]};
    const float* mw  = (const float*)d_in[13];
    const float* mb  = (const float*)d_in[14];
    const float* ng  = (const float*)d_in[15];
    const float* nb  = (const float*)d_in[16];
    const float* fw1 = (const float*)d_in[17];
    const float* fb1 = (const float*)d_in[18];
    const float* fw2 = (const float*)d_in[19];
    const float* fb2 = (const float*)d_in[20];
    const float* fng = (const float*)d_in[21];
    const float* fnb = (const float*)d_in[22];
    float* out = (float*)d_out;

    float *p_res,*p_cv,*p_x1,*p_xf,*p_xi,*p_xr,*p_yln,*p_y2,*p_br,*p_mg,*p_h1,*p_h2,*p_W2,*p_Wm,*p_CM,*p_CM2;
    cudaGetSymbolAddress((void**)&p_res, g_res);
    cudaGetSymbolAddress((void**)&p_cv,  g_cv);
    cudaGetSymbolAddress((void**)&p_x1,  g_x1);
    cudaGetSymbolAddress((void**)&p_xf,  g_xf);
    cudaGetSymbolAddress((void**)&p_xi,  g_xi);
    cudaGetSymbolAddress((void**)&p_xr,  g_xr);
    cudaGetSymbolAddress((void**)&p_yln, g_yln);
    cudaGetSymbolAddress((void**)&p_y2,  g_y2);
    cudaGetSymbolAddress((void**)&p_br,  g_br);
    cudaGetSymbolAddress((void**)&p_mg,  g_mg);
    cudaGetSymbolAddress((void**)&p_h1,  g_h1);
    cudaGetSymbolAddress((void**)&p_h2,  g_h2);
    cudaGetSymbolAddress((void**)&p_W2,  g_W2);
    cudaGetSymbolAddress((void**)&p_Wm,  g_Wm);
    cudaGetSymbolAddress((void**)&p_CM,  g_CM);
    cudaGetSymbolAddress((void**)&p_CM2, g_CM2);

    decomp_kernel<<<dim3(NL/32, NC/32, NB), dim3(32, 32)>>>(src, p_res);
    prep_merge_k<<<1024, 256>>>(mw, p_Wm);

    const int Kk[2] = {12, 24}, PD[2] = {6, 12}, NE[2] = {43, 22},
              MM[2] = {85, 43}, N2_[2] = {169, 85}, MKl[2] = {1020, 1032};

    for (int n = 0; n < 2; n++) {
        int k = Kk[n], pad = PD[n], ne = NE[n], m = MM[n], N2 = N2_[n], mk = MKl[n];
        int ne2 = 2*ne;
        build_cm_k<<<256, 256>>>(p_CM, p_CM2, m, N2);
        prep_trw_k<<<4096, 256>>>(tw[n], p_W2, k);

        { // strided conv (even+odd interleaved), tanh
            GemmP p{};
            p.A = cw[n]; p.lda = NC*k;
            p.Bp = p_res + (size_t)n*NB*NC*NL; p.sBb = (long long)NC*NL;
            p.kker = k; p.pad = pad; p.lhalf = LH; p.inner = NL;
            p.D = p_cv; p.sDb = (long long)NC*ne2; p.ldd = ne2;
            p.bias = cb[n];
            p.M = NC; p.N = NB*ne2; p.K = NC*k; p.npos = ne2;
            gemm_k<1,1,1,0><<<gemm_grid(p.M, p.N), 256>>>(p);
        }
        x1_kernel<<<1024, 256>>>(p_cv, p_x1, m, ne2);
        { // real-DFT
            GemmP p{};
            p.A = p_x1; p.lda = m;
            p.Bp = p_CM; p.ldb = N2; p.sBb = 0;
            p.D = p_xf; p.sDb = 0; p.ldd = N2;
            p.M = NB*NC; p.N = N2; p.K = m; p.npos = N2;
            gemm_k<0,0,0,0><<<gemm_grid(p.M, p.N), 256>>>(p);
        }
        { // isometric conv (valid), tanh
            GemmP p{};
            p.A = iw[n]; p.lda = NC*m;
            p.Bp = p_xf; p.sBb = (long long)NC*N2; p.kker = m; p.inner = N2;
            p.D = p_xi; p.sDb = (long long)NC*m; p.ldd = m;
            p.bias = ib[n];
            p.M = NC; p.N = NB*m; p.K = NC*m; p.npos = m;
            gemm_k<2,1,1,0><<<gemm_grid(p.M, p.N), 256>>>(p);
        }
        { // real-IDFT
            GemmP p{};
            p.A = p_xi; p.lda = m;
            p.Bp = p_CM2; p.ldb = m; p.sBb = 0;
            p.D = p_xr; p.sDb = 0; p.ldd = m;
            p.M = NB*NC; p.N = m; p.K = m; p.npos = m;
            gemm_k<0,0,0,0><<<gemm_grid(p.M, p.N), 256>>>(p);
        }
        ln1_kernel<<<NB*m, 256>>>(p_xr, p_x1, ng, nb, p_yln, m);
        { // conv-transpose (stride==kernel), tanh, scatter store
            GemmP p{};
            p.A = p_W2; p.lda = NC;
            p.Bp = p_yln; p.ldb = m; p.sBb = (long long)NC*m;
            p.D = p_y2; p.sDb = (long long)NC*mk; p.kt = k; p.mklen = mk;
            p.bias = tb[n];
            p.M = NC*k; p.N = NB*m; p.K = NC; p.npos = m;
            gemm_k<0,3,1,1><<<gemm_grid(p.M, p.N), 256>>>(p);
        }
        branch_out_kernel<<<NB*NL, 256>>>(p_y2, p_res + (size_t)n*NB*NC*NL, ng, nb, p_br, mk, n);
    }
    { // merge (branches x channels contraction)
        GemmP p{};
        p.A = p_br; p.lda = 2*NC;
        p.Bp = p_Wm; p.ldb = NC; p.sBb = 0;
        p.D = p_mg; p.sDb = 0; p.ldd = NC;
        p.bias = mb;
        p.M = NB*NL; p.N = NC; p.K = 2*NC; p.npos = NC;
        gemm_k<0,2,0,0><<<gemm_grid(p.M, p.N), 256>>>(p);
    }
    { // FFN layer 1 (relu)
        GemmP p{};
        p.A = p_mg; p.lda = NC;
        p.Bp = fw1; p.ldb = 4*NC; p.sBb = 0;
        p.D = p_h1; p.sDb = 0; p.ldd = 4*NC;
        p.bias = fb1;
        p.M = NB*NL; p.N = 4*NC; p.K = NC; p.npos = 4*NC;
        gemm_k<0,2,2,0><<<gemm_grid(p.M, p.N), 256>>>(p);
    }
    { // FFN layer 2
        GemmP p{};
        p.A = p_h1; p.lda = 4*NC;
        p.Bp = fw2; p.ldb = NC; p.sBb = 0;
        p.D = p_h2; p.sDb = 0; p.ldd = NC;
        p.bias = fb2;
        p.M = NB*NL; p.N = NC; p.K = 4*NC; p.npos = NC;
        gemm_k<0,2,0,0><<<gemm_grid(p.M, p.N), 256>>>(p);
    }
    final_ln_kernel<<<NB*NL, 256>>>(p_mg, p_h2, fng, fnb, out);
}